// round 1
// baseline (speedup 1.0000x reference)
#include <cuda_runtime.h>
#include <math.h>

#define En 1024
#define Hn 16
#define Dh 64
#define Sn 2048
#define Bn 2
#define Mtot (Bn*Sn)      // 4096
#define FFdim (4*En)      // 4096

// ---------------- scratch (static device arrays; no allocations) ----------------
__device__ __align__(256) float g_nx [Mtot*En];
__device__ __align__(256) float g_q  [Mtot*En];
__device__ __align__(256) float g_k  [Mtot*En];
__device__ __align__(256) float g_v  [Mtot*En];
__device__ __align__(256) float g_ao [Mtot*En];
__device__ __align__(256) float g_x2 [Mtot*En];
__device__ __align__(256) float g_nx2[Mtot*En];
__device__ __align__(256) float g_h  [Mtot*FFdim];

// ---------------- LayerNorm (matches ref: unbiased var, /(std+eps)) ----------------
__global__ void ln_kernel(const float* __restrict__ x, const float* __restrict__ w,
                          const float* __restrict__ b, float* __restrict__ y) {
    int row = blockIdx.x;
    const float* xr = x + (size_t)row * En;
    __shared__ float red[256];
    int tid = threadIdx.x;

    float s = 0.f;
    for (int i = tid; i < En; i += 256) s += xr[i];
    red[tid] = s; __syncthreads();
    for (int off = 128; off > 0; off >>= 1) {
        if (tid < off) red[tid] += red[tid + off];
        __syncthreads();
    }
    float mean = red[0] * (1.0f / En);
    __syncthreads();

    float s2 = 0.f;
    for (int i = tid; i < En; i += 256) { float d = xr[i] - mean; s2 += d * d; }
    red[tid] = s2; __syncthreads();
    for (int off = 128; off > 0; off >>= 1) {
        if (tid < off) red[tid] += red[tid + off];
        __syncthreads();
    }
    float var = red[0] * (1.0f / (En - 1));
    float inv = 1.0f / (sqrtf(var) + 1e-5f);

    float* yr = y + (size_t)row * En;
    for (int i = tid; i < En; i += 256)
        yr[i] = w[i] * (xr[i] - mean) * inv + b[i];
}

// ---------------- SGEMM: C[m,n] = sum_k A[m,k]*W[n,k] + bias[n] (+res, relu) -------
// A: [M,K] row-major, W: [N,K] row-major. BM=BN=128, BK=8, 256 threads, 8x8 microtile.
template<bool RELU, bool RES>
__global__ __launch_bounds__(256)
void gemm_kernel(const float* __restrict__ A, const float* __restrict__ W,
                 const float* __restrict__ bias, const float* __restrict__ R,
                 float* __restrict__ C, int M, int N, int K) {
    const int BM = 128, BN = 128, BK = 8;
    __shared__ float As[BK][BM];
    __shared__ float Ws[BK][BN];

    int m0 = blockIdx.y * BM, n0 = blockIdx.x * BN;
    int tid = threadIdx.x;
    int tx = tid & 15, ty = tid >> 4;

    float acc[8][8];
    #pragma unroll
    for (int i = 0; i < 8; i++)
        #pragma unroll
        for (int j = 0; j < 8; j++) acc[i][j] = 0.f;

    int lr = tid >> 1;            // 0..127
    int lc = (tid & 1) * 4;       // 0 or 4
    const float* Aptr = A + (size_t)(m0 + lr) * K + lc;
    const float* Wptr = W + (size_t)(n0 + lr) * K + lc;

    for (int k0 = 0; k0 < K; k0 += BK) {
        float4 av = *(const float4*)(Aptr + k0);
        float4 wv = *(const float4*)(Wptr + k0);
        As[lc + 0][lr] = av.x; As[lc + 1][lr] = av.y;
        As[lc + 2][lr] = av.z; As[lc + 3][lr] = av.w;
        Ws[lc + 0][lr] = wv.x; Ws[lc + 1][lr] = wv.y;
        Ws[lc + 2][lr] = wv.z; Ws[lc + 3][lr] = wv.w;
        __syncthreads();

        #pragma unroll
        for (int kk = 0; kk < BK; kk++) {
            const float4* Ask = (const float4*)&As[kk][0];
            const float4* Wsk = (const float4*)&Ws[kk][0];
            float4 a0 = Ask[ty], a1 = Ask[16 + ty];
            float4 b0 = Wsk[tx], b1 = Wsk[16 + tx];
            float a[8] = {a0.x,a0.y,a0.z,a0.w, a1.x,a1.y,a1.z,a1.w};
            float bb[8] = {b0.x,b0.y,b0.z,b0.w, b1.x,b1.y,b1.z,b1.w};
            #pragma unroll
            for (int i = 0; i < 8; i++)
                #pragma unroll
                for (int j = 0; j < 8; j++)
                    acc[i][j] += a[i] * bb[j];
        }
        __syncthreads();
    }

    #pragma unroll
    for (int i = 0; i < 8; i++) {
        int m = m0 + ((i < 4) ? (ty * 4 + i) : (64 + ty * 4 + (i - 4)));
        #pragma unroll
        for (int j = 0; j < 8; j++) {
            int n = n0 + ((j < 4) ? (tx * 4 + j) : (64 + tx * 4 + (j - 4)));
            float c = acc[i][j] + bias[n];
            if (RES) c += R[(size_t)m * N + n];
            if (RELU) c = fmaxf(c, 0.f);
            C[(size_t)m * N + n] = c;
        }
    }
}

// ---------------- Flash attention (online softmax), 64 queries/block ---------------
// Q,K,V,O all in [B,S,E] layout; head h occupies columns [h*64, h*64+64).
__global__ __launch_bounds__(64)
void attn_kernel(const float* __restrict__ Q, const float* __restrict__ Kt,
                 const float* __restrict__ V, const int* __restrict__ mask,
                 float* __restrict__ O) {
    int h = blockIdx.y, b = blockIdx.z;
    int tid = threadIdx.x;
    int s = blockIdx.x * 64 + tid;

    __shared__ float4 ks[64][16];
    __shared__ float4 vs[64][16];

    const float4* Qr = (const float4*)(Q + ((size_t)(b * Sn + s)) * En + h * Dh);
    float4 q[16];
    #pragma unroll
    for (int j = 0; j < 16; j++) q[j] = Qr[j];

    float4 o[16];
    #pragma unroll
    for (int j = 0; j < 16; j++) o[j] = make_float4(0.f, 0.f, 0.f, 0.f);
    float mrun = -1e30f, lrun = 0.f;

    const int* mrow = mask + ((size_t)(b * Sn + s)) * Sn;

    int r = tid >> 4;   // 0..3
    int c = tid & 15;   // 0..15

    for (int t0 = 0; t0 < Sn; t0 += 64) {
        #pragma unroll
        for (int i = 0; i < 16; i++) {
            int row = i * 4 + r;
            const float4* Kr = (const float4*)(Kt + ((size_t)(b * Sn + t0 + row)) * En + h * Dh);
            const float4* Vr = (const float4*)(V  + ((size_t)(b * Sn + t0 + row)) * En + h * Dh);
            ks[row][c] = Kr[c];
            vs[row][c] = Vr[c];
        }
        __syncthreads();

        for (int t = 0; t < 64; t++) {
            float dot = 0.f;
            #pragma unroll
            for (int j = 0; j < 16; j++) {
                float4 kv = ks[t][j];
                dot += q[j].x * kv.x + q[j].y * kv.y + q[j].z * kv.z + q[j].w * kv.w;
            }
            dot *= 0.125f;   // D^-0.5
            if (mrow[t0 + t] != 0) {
                if (dot > mrun) {
                    float corr = __expf(mrun - dot);
                    mrun = dot;
                    lrun *= corr;
                    #pragma unroll
                    for (int j = 0; j < 16; j++) {
                        o[j].x *= corr; o[j].y *= corr; o[j].z *= corr; o[j].w *= corr;
                    }
                }
                float p = __expf(dot - mrun);
                lrun += p;
                #pragma unroll
                for (int j = 0; j < 16; j++) {
                    float4 vv = vs[t][j];
                    o[j].x += p * vv.x; o[j].y += p * vv.y;
                    o[j].z += p * vv.z; o[j].w += p * vv.w;
                }
            }
        }
        __syncthreads();
    }

    float inv = 1.0f / lrun;
    float4* Or = (float4*)(O + ((size_t)(b * Sn + s)) * En + h * Dh);
    #pragma unroll
    for (int j = 0; j < 16; j++) {
        float4 t = o[j];
        t.x *= inv; t.y *= inv; t.z *= inv; t.w *= inv;
        Or[j] = t;
    }
}

// ---------------- launch ----------------
extern "C" void kernel_launch(void* const* d_in, const int* in_sizes, int n_in,
                              void* d_out, int out_size) {
    const float* x    = (const float*)d_in[0];
    const int*   mask = (const int*)  d_in[1];
    const float* wq = (const float*)d_in[2],  * bq = (const float*)d_in[3];
    const float* wk = (const float*)d_in[4],  * bk = (const float*)d_in[5];
    const float* wv = (const float*)d_in[6],  * bv = (const float*)d_in[7];
    const float* wo = (const float*)d_in[8],  * bo = (const float*)d_in[9];
    const float* w1 = (const float*)d_in[10], * b1 = (const float*)d_in[11];
    const float* w2 = (const float*)d_in[12], * b2 = (const float*)d_in[13];
    const float* ln1w = (const float*)d_in[14], * ln1b = (const float*)d_in[15];
    const float* ln2w = (const float*)d_in[16], * ln2b = (const float*)d_in[17];
    float* out = (float*)d_out;

    float *nx, *q, *k, *v, *ao, *x2, *nx2, *hb;
    cudaGetSymbolAddress((void**)&nx,  g_nx);
    cudaGetSymbolAddress((void**)&q,   g_q);
    cudaGetSymbolAddress((void**)&k,   g_k);
    cudaGetSymbolAddress((void**)&v,   g_v);
    cudaGetSymbolAddress((void**)&ao,  g_ao);
    cudaGetSymbolAddress((void**)&x2,  g_x2);
    cudaGetSymbolAddress((void**)&nx2, g_nx2);
    cudaGetSymbolAddress((void**)&hb,  g_h);

    // 1) LN1
    ln_kernel<<<Mtot, 256>>>(x, ln1w, ln1b, nx);

    // 2-4) Q,K,V projections ([4096,1024] x [1024,1024]^T)
    dim3 gProj(En / 128, Mtot / 128);
    gemm_kernel<false, false><<<gProj, 256>>>(nx, wq, bq, nullptr, q, Mtot, En, En);
    gemm_kernel<false, false><<<gProj, 256>>>(nx, wk, bk, nullptr, k, Mtot, En, En);
    gemm_kernel<false, false><<<gProj, 256>>>(nx, wv, bv, nullptr, v, Mtot, En, En);

    // 5) attention
    dim3 gAttn(Sn / 64, Hn, Bn);
    attn_kernel<<<gAttn, 64>>>(q, k, v, mask, ao);

    // 6) O projection + residual -> x2
    gemm_kernel<false, true><<<gProj, 256>>>(ao, wo, bo, x, x2, Mtot, En, En);

    // 7) LN2
    ln_kernel<<<Mtot, 256>>>(x2, ln2w, ln2b, nx2);

    // 8) FFN1 + ReLU ([4096,1024] x [4096,1024]^T)
    dim3 gF1(FFdim / 128, Mtot / 128);
    gemm_kernel<true, false><<<gF1, 256>>>(nx2, w1, b1, nullptr, hb, Mtot, FFdim, En);

    // 9) FFN2 + residual -> out ([4096,4096] x [1024,4096]^T)
    dim3 gF2(En / 128, Mtot / 128);
    gemm_kernel<false, true><<<gF2, 256>>>(hb, w2, b2, x2, out, Mtot, En, FFdim);
}

// round 3
// speedup vs baseline: 1.4518x; 1.4518x over previous
#include <cuda_runtime.h>
#include <cuda_bf16.h>
#include <math.h>
#include <stdint.h>

#define En 1024
#define Hn 16
#define Dh 64
#define Sn 2048
#define Bn 2
#define Mtot (Bn*Sn)      // 4096
#define FFdim (4*En)      // 4096

// ---------------- scratch (static device arrays; no allocations) ----------------
__device__ __align__(256) float g_q [Mtot*En];
__device__ __align__(256) float g_k [Mtot*En];
__device__ __align__(256) float g_v [Mtot*En];
__device__ __align__(256) float g_x2[Mtot*En];

__device__ __align__(256) __nv_bfloat16 g_nx_h [Mtot*En];
__device__ __align__(256) __nv_bfloat16 g_nx_l [Mtot*En];
__device__ __align__(256) __nv_bfloat16 g_ao_h [Mtot*En];
__device__ __align__(256) __nv_bfloat16 g_ao_l [Mtot*En];
__device__ __align__(256) __nv_bfloat16 g_nx2_h[Mtot*En];
__device__ __align__(256) __nv_bfloat16 g_nx2_l[Mtot*En];
__device__ __align__(256) __nv_bfloat16 g_hb_h [Mtot*FFdim];
__device__ __align__(256) __nv_bfloat16 g_hb_l [Mtot*FFdim];

__device__ __align__(256) __nv_bfloat16 g_wq_h[En*En],    g_wq_l[En*En];
__device__ __align__(256) __nv_bfloat16 g_wk_h[En*En],    g_wk_l[En*En];
__device__ __align__(256) __nv_bfloat16 g_wv_h[En*En],    g_wv_l[En*En];
__device__ __align__(256) __nv_bfloat16 g_wo_h[En*En],    g_wo_l[En*En];
__device__ __align__(256) __nv_bfloat16 g_w1_h[FFdim*En], g_w1_l[FFdim*En];
__device__ __align__(256) __nv_bfloat16 g_w2_h[En*FFdim], g_w2_l[En*FFdim];

// ---------------- helpers ----------------
__device__ __forceinline__ uint32_t s2u(const void* p) {
    uint32_t a;
    asm("{ .reg .u64 t; cvta.to.shared.u64 t, %1; cvt.u32.u64 %0, t; }" : "=r"(a) : "l"(p));
    return a;
}
__device__ __forceinline__ void split2(float f, __nv_bfloat16& h, __nv_bfloat16& l) {
    h = __float2bfloat16(f);
    l = __float2bfloat16(f - __bfloat162float(h));
}
__device__ __forceinline__ void ldsm4(uint32_t& r0, uint32_t& r1, uint32_t& r2, uint32_t& r3, uint32_t a) {
    asm volatile("ldmatrix.sync.aligned.m8n8.x4.shared.b16 {%0,%1,%2,%3},[%4];"
                 : "=r"(r0), "=r"(r1), "=r"(r2), "=r"(r3) : "r"(a));
}
__device__ __forceinline__ void mma16816(float* d, const uint32_t* a, const uint32_t* b) {
    asm volatile("mma.sync.aligned.m16n8k16.row.col.f32.bf16.bf16.f32 "
                 "{%0,%1,%2,%3},{%4,%5,%6,%7},{%8,%9},{%0,%1,%2,%3};"
                 : "+f"(d[0]), "+f"(d[1]), "+f"(d[2]), "+f"(d[3])
                 : "r"(a[0]), "r"(a[1]), "r"(a[2]), "r"(a[3]), "r"(b[0]), "r"(b[1]));
}
#define CP16(dst, src) asm volatile("cp.async.cg.shared.global [%0],[%1],16;" :: "r"(dst), "l"(src))
#define CP_COMMIT()    asm volatile("cp.async.commit_group;" ::: "memory")
#define CP_WAIT1()     asm volatile("cp.async.wait_group 1;" ::: "memory")
#define CP_WAIT0()     asm volatile("cp.async.wait_group 0;" ::: "memory")

// ---------------- weight fp32 -> (hi,lo) bf16 split ----------------
__global__ void cvt_split(const float4* __restrict__ src, __nv_bfloat162* __restrict__ h,
                          __nv_bfloat162* __restrict__ l, int n4) {
    int i = blockIdx.x * 256 + threadIdx.x;
    if (i < n4) {
        float4 v = src[i];
        __nv_bfloat16 h0, l0, h1, l1, h2, l2, h3, l3;
        split2(v.x, h0, l0); split2(v.y, h1, l1);
        split2(v.z, h2, l2); split2(v.w, h3, l3);
        h[2 * i]     = __halves2bfloat162(h0, h1);
        h[2 * i + 1] = __halves2bfloat162(h2, h3);
        l[2 * i]     = __halves2bfloat162(l0, l1);
        l[2 * i + 1] = __halves2bfloat162(l2, l3);
    }
}

// ---------------- LayerNorm -> split bf16 (unbiased var, /(std+eps)) ----------------
__global__ void ln_split(const float* __restrict__ x, const float* __restrict__ w,
                         const float* __restrict__ b,
                         __nv_bfloat16* __restrict__ H, __nv_bfloat16* __restrict__ L) {
    int row = blockIdx.x;
    const float* xr = x + (size_t)row * En;
    __shared__ float red[256];
    int tid = threadIdx.x;

    float s = 0.f;
    for (int i = tid; i < En; i += 256) s += xr[i];
    red[tid] = s; __syncthreads();
    for (int off = 128; off > 0; off >>= 1) {
        if (tid < off) red[tid] += red[tid + off];
        __syncthreads();
    }
    float mean = red[0] * (1.0f / En);
    __syncthreads();

    float s2 = 0.f;
    for (int i = tid; i < En; i += 256) { float d = xr[i] - mean; s2 += d * d; }
    red[tid] = s2; __syncthreads();
    for (int off = 128; off > 0; off >>= 1) {
        if (tid < off) red[tid] += red[tid + off];
        __syncthreads();
    }
    float var = red[0] * (1.0f / (En - 1));
    float inv = 1.0f / (sqrtf(var) + 1e-5f);

    int i0 = tid * 4;
    float4 xv = *(const float4*)(xr + i0);
    float4 wv = *(const float4*)(w + i0);
    float4 bv = *(const float4*)(b + i0);
    float y0 = wv.x * (xv.x - mean) * inv + bv.x;
    float y1 = wv.y * (xv.y - mean) * inv + bv.y;
    float y2 = wv.z * (xv.z - mean) * inv + bv.z;
    float y3 = wv.w * (xv.w - mean) * inv + bv.w;
    __nv_bfloat16 h0, l0, h1, l1, h2, l2, h3, l3;
    split2(y0, h0, l0); split2(y1, h1, l1); split2(y2, h2, l2); split2(y3, h3, l3);
    __nv_bfloat162* Hr = (__nv_bfloat162*)(H + (size_t)row * En + i0);
    __nv_bfloat162* Lr = (__nv_bfloat162*)(L + (size_t)row * En + i0);
    Hr[0] = __halves2bfloat162(h0, h1); Hr[1] = __halves2bfloat162(h2, h3);
    Lr[0] = __halves2bfloat162(l0, l1); Lr[1] = __halves2bfloat162(l2, l3);
}

// ---------------- split-bf16 GEMM via mma.sync: C = A @ W^T (+bias, +res, relu) -----
// A: [M,K], W: [N,K], (hi,lo) bf16 K-major. Tile 128x128, BK=32, 256 thr, 8 warps.
// Warp layout: 4 (m) x 2 (n); warp tile 32x64; mma m16n8k16.
#define PITCHB 80                     // smem row pitch bytes (32 bf16 + 8 pad)
#define ARR_BYTES (128 * PITCHB)      // 10240
#define STAGE_BYTES (4 * ARR_BYTES)   // 40960: [Ah | Al | Wh | Wl]
#define SMEM_DYN (2 * STAGE_BYTES)    // 81920

enum { OUT_F32 = 0, OUT_SPLIT = 1 };

template<int OUTM, bool RELU, bool RES>
__global__ __launch_bounds__(256, 1)
void bf_gemm(const __nv_bfloat16* __restrict__ Ah, const __nv_bfloat16* __restrict__ Al,
             const __nv_bfloat16* __restrict__ Wh, const __nv_bfloat16* __restrict__ Wl,
             const float* __restrict__ bias, const float* __restrict__ R,
             float* __restrict__ Cf, __nv_bfloat16* __restrict__ Ch, __nv_bfloat16* __restrict__ Cl,
             int M, int N, int K) {
    extern __shared__ char sm[];
    uint32_t sb = s2u(sm);

    int tid = threadIdx.x;
    int lane = tid & 31, wid = tid >> 5;
    int wm = wid & 3, wn = wid >> 2;
    int m0 = blockIdx.y * 128, n0 = blockIdx.x * 128;

    const size_t rowB = (size_t)K * 2;
    const char* pAh = (const char*)Ah + (size_t)m0 * rowB;
    const char* pAl = (const char*)Al + (size_t)m0 * rowB;
    const char* pWh = (const char*)Wh + (size_t)n0 * rowB;
    const char* pWl = (const char*)Wl + (size_t)n0 * rowB;

    float acc[2][8][4];
    #pragma unroll
    for (int i = 0; i < 2; i++)
        #pragma unroll
        for (int j = 0; j < 8; j++)
            #pragma unroll
            for (int t = 0; t < 4; t++) acc[i][j][t] = 0.f;

    int nc = K / 32;

    // ---- stage loader (cp.async, 8x16B per thread) ----
    auto load_stage = [&](int kc) {
        uint32_t st = sb + (kc & 1) * STAGE_BYTES;
        size_t gk = (size_t)kc * 64;   // 32 bf16 = 64 bytes
        #pragma unroll
        for (int half = 0; half < 2; half++) {
            int v = tid + half * 256;
            int r = v >> 2, c = v & 3;
            uint32_t dst = st + r * PITCHB + c * 16;
            size_t go = (size_t)r * rowB + gk + (size_t)c * 16;
            CP16(dst,                 pAh + go);
            CP16(dst + ARR_BYTES,     pAl + go);
            CP16(dst + 2 * ARR_BYTES, pWh + go);
            CP16(dst + 3 * ARR_BYTES, pWl + go);
        }
    };

    load_stage(0);
    CP_COMMIT();

    // precomputed intra-warp smem offsets
    uint32_t aRow = wm * 32 + (lane & 15);
    uint32_t aCol = 8 * (lane >> 4);
    uint32_t bRow = wn * 64 + (lane & 7) + 8 * (lane >> 4);
    uint32_t bCol = 8 * ((lane >> 3) & 1);

    for (int kc = 0; kc < nc; kc++) {
        if (kc + 1 < nc) { load_stage(kc + 1); CP_COMMIT(); CP_WAIT1(); }
        else             { CP_WAIT0(); }
        __syncthreads();

        uint32_t st = sb + (kc & 1) * STAGE_BYTES;
        #pragma unroll
        for (int ks = 0; ks < 2; ks++) {
            int k0 = ks * 16;
            uint32_t ah[2][4], al[2][4];
            #pragma unroll
            for (int mt = 0; mt < 2; mt++) {
                uint32_t ad = st + (aRow + mt * 16) * PITCHB + (k0 + aCol) * 2;
                ldsm4(ah[mt][0], ah[mt][1], ah[mt][2], ah[mt][3], ad);
                ldsm4(al[mt][0], al[mt][1], al[mt][2], al[mt][3], ad + ARR_BYTES);
            }
            uint32_t bh[8][2], bl[8][2];
            #pragma unroll
            for (int nt2 = 0; nt2 < 4; nt2++) {
                uint32_t bd = st + 2 * ARR_BYTES + (bRow + nt2 * 16) * PITCHB + (k0 + bCol) * 2;
                uint32_t t0, t1, t2, t3;
                ldsm4(t0, t1, t2, t3, bd);
                bh[2 * nt2][0] = t0; bh[2 * nt2][1] = t1;
                bh[2 * nt2 + 1][0] = t2; bh[2 * nt2 + 1][1] = t3;
                ldsm4(t0, t1, t2, t3, bd + ARR_BYTES);
                bl[2 * nt2][0] = t0; bl[2 * nt2][1] = t1;
                bl[2 * nt2 + 1][0] = t2; bl[2 * nt2 + 1][1] = t3;
            }
            #pragma unroll
            for (int mt = 0; mt < 2; mt++)
                #pragma unroll
                for (int nt = 0; nt < 8; nt++) {
                    mma16816(acc[mt][nt], ah[mt], bh[nt]);
                    mma16816(acc[mt][nt], ah[mt], bl[nt]);
                    mma16816(acc[mt][nt], al[mt], bh[nt]);
                }
        }
        __syncthreads();
    }

    // ---- epilogue ----
    int lr = lane >> 2, lc = (lane & 3) * 2;
    int mb = m0 + wm * 32;
    int nb = n0 + wn * 64;
    #pragma unroll
    for (int mt = 0; mt < 2; mt++) {
        #pragma unroll
        for (int nt = 0; nt < 8; nt++) {
            const float* a = acc[mt][nt];
            int col = nb + nt * 8 + lc;
            float b0 = bias[col], b1 = bias[col + 1];
            #pragma unroll
            for (int h = 0; h < 2; h++) {   // h=0: rows lr, h=1: rows lr+8
                int row = mb + mt * 16 + lr + h * 8;
                float f0 = a[2 * h + 0] + b0;
                float f1 = a[2 * h + 1] + b1;
                if (RES) {
                    const float2 rv = *(const float2*)(R + (size_t)row * N + col);
                    f0 += rv.x; f1 += rv.y;
                }
                if (RELU) { f0 = fmaxf(f0, 0.f); f1 = fmaxf(f1, 0.f); }
                if (OUTM == OUT_F32) {
                    *(float2*)(Cf + (size_t)row * N + col) = make_float2(f0, f1);
                } else {
                    __nv_bfloat16 h0, l0, h1, l1;
                    split2(f0, h0, l0); split2(f1, h1, l1);
                    *(__nv_bfloat162*)(Ch + (size_t)row * N + col) = __halves2bfloat162(h0, h1);
                    *(__nv_bfloat162*)(Cl + (size_t)row * N + col) = __halves2bfloat162(l0, l1);
                }
            }
        }
    }
}

// ---------------- Flash attention (fp32, online softmax) -> split bf16 out ---------
__global__ __launch_bounds__(64)
void attn_kernel(const float* __restrict__ Q, const float* __restrict__ Kt,
                 const float* __restrict__ V, const int* __restrict__ mask,
                 __nv_bfloat16* __restrict__ OH, __nv_bfloat16* __restrict__ OL) {
    int h = blockIdx.y, b = blockIdx.z;
    int tid = threadIdx.x;
    int s = blockIdx.x * 64 + tid;

    __shared__ float4 ks[64][16];
    __shared__ float4 vs[64][16];

    const float4* Qr = (const float4*)(Q + ((size_t)(b * Sn + s)) * En + h * Dh);
    float4 q[16];
    #pragma unroll
    for (int j = 0; j < 16; j++) q[j] = Qr[j];

    float4 o[16];
    #pragma unroll
    for (int j = 0; j < 16; j++) o[j] = make_float4(0.f, 0.f, 0.f, 0.f);
    float mrun = -1e30f, lrun = 0.f;

    const int* mrow = mask + ((size_t)(b * Sn + s)) * Sn;
    int r = tid >> 4, c = tid & 15;

    for (int t0 = 0; t0 < Sn; t0 += 64) {
        #pragma unroll
        for (int i = 0; i < 16; i++) {
            int row = i * 4 + r;
            const float4* Kr = (const float4*)(Kt + ((size_t)(b * Sn + t0 + row)) * En + h * Dh);
            const float4* Vr = (const float4*)(V  + ((size_t)(b * Sn + t0 + row)) * En + h * Dh);
            ks[row][c] = Kr[c];
            vs[row][c] = Vr[c];
        }
        __syncthreads();

        for (int t = 0; t < 64; t++) {
            float dot = 0.f;
            #pragma unroll
            for (int j = 0; j < 16; j++) {
                float4 kv = ks[t][j];
                dot += q[j].x * kv.x + q[j].y * kv.y + q[j].z * kv.z + q[j].w * kv.w;
            }
            dot *= 0.125f;
            if (mrow[t0 + t] != 0) {
                if (dot > mrun) {
                    float corr = __expf(mrun - dot);
                    mrun = dot;
                    lrun *= corr;
                    #pragma unroll
                    for (int j = 0; j < 16; j++) {
                        o[j].x *= corr; o[j].y *= corr; o[j].z *= corr; o[j].w *= corr;
                    }
                }
                float p = __expf(dot - mrun);
                lrun += p;
                #pragma unroll
                for (int j = 0; j < 16; j++) {
                    float4 vv = vs[t][j];
                    o[j].x += p * vv.x; o[j].y += p * vv.y;
                    o[j].z += p * vv.z; o[j].w += p * vv.w;
                }
            }
        }
        __syncthreads();
    }

    float inv = 1.0f / lrun;
    size_t base = ((size_t)(b * Sn + s)) * En + h * Dh;
    __nv_bfloat162* oh = (__nv_bfloat162*)(OH + base);
    __nv_bfloat162* ol = (__nv_bfloat162*)(OL + base);
    #pragma unroll
    for (int j = 0; j < 16; j++) {
        float4 t = o[j];
        t.x *= inv; t.y *= inv; t.z *= inv; t.w *= inv;
        __nv_bfloat16 h0, l0, h1, l1, h2, l2, h3, l3;
        split2(t.x, h0, l0); split2(t.y, h1, l1);
        split2(t.z, h2, l2); split2(t.w, h3, l3);
        oh[2 * j]     = __halves2bfloat162(h0, h1);
        oh[2 * j + 1] = __halves2bfloat162(h2, h3);
        ol[2 * j]     = __halves2bfloat162(l0, l1);
        ol[2 * j + 1] = __halves2bfloat162(l2, l3);
    }
}

// ---------------- launch ----------------
extern "C" void kernel_launch(void* const* d_in, const int* in_sizes, int n_in,
                              void* d_out, int out_size) {
    const float* x    = (const float*)d_in[0];
    const int*   mask = (const int*)  d_in[1];
    const float* wq = (const float*)d_in[2],  * bq = (const float*)d_in[3];
    const float* wk = (const float*)d_in[4],  * bk = (const float*)d_in[5];
    const float* wv = (const float*)d_in[6],  * bv = (const float*)d_in[7];
    const float* wo = (const float*)d_in[8],  * bo = (const float*)d_in[9];
    const float* w1 = (const float*)d_in[10], * b1 = (const float*)d_in[11];
    const float* w2 = (const float*)d_in[12], * b2 = (const float*)d_in[13];
    const float* ln1w = (const float*)d_in[14], * ln1b = (const float*)d_in[15];
    const float* ln2w = (const float*)d_in[16], * ln2b = (const float*)d_in[17];
    float* out = (float*)d_out;

    float *q, *k, *v, *x2;
    cudaGetSymbolAddress((void**)&q,  g_q);
    cudaGetSymbolAddress((void**)&k,  g_k);
    cudaGetSymbolAddress((void**)&v,  g_v);
    cudaGetSymbolAddress((void**)&x2, g_x2);

    __nv_bfloat16 *nxh, *nxl, *aoh, *aol, *nx2h, *nx2l, *hbh, *hbl;
    __nv_bfloat16 *wqh, *wql, *wkh, *wkl, *wvh, *wvl, *woh, *wol, *w1h, *w1l, *w2h, *w2l;
    cudaGetSymbolAddress((void**)&nxh,  g_nx_h);  cudaGetSymbolAddress((void**)&nxl,  g_nx_l);
    cudaGetSymbolAddress((void**)&aoh,  g_ao_h);  cudaGetSymbolAddress((void**)&aol,  g_ao_l);
    cudaGetSymbolAddress((void**)&nx2h, g_nx2_h); cudaGetSymbolAddress((void**)&nx2l, g_nx2_l);
    cudaGetSymbolAddress((void**)&hbh,  g_hb_h);  cudaGetSymbolAddress((void**)&hbl,  g_hb_l);
    cudaGetSymbolAddress((void**)&wqh, g_wq_h); cudaGetSymbolAddress((void**)&wql, g_wq_l);
    cudaGetSymbolAddress((void**)&wkh, g_wk_h); cudaGetSymbolAddress((void**)&wkl, g_wk_l);
    cudaGetSymbolAddress((void**)&wvh, g_wv_h); cudaGetSymbolAddress((void**)&wvl, g_wv_l);
    cudaGetSymbolAddress((void**)&woh, g_wo_h); cudaGetSymbolAddress((void**)&wol, g_wo_l);
    cudaGetSymbolAddress((void**)&w1h, g_w1_h); cudaGetSymbolAddress((void**)&w1l, g_w1_l);
    cudaGetSymbolAddress((void**)&w2h, g_w2_h); cudaGetSymbolAddress((void**)&w2l, g_w2_l);

    cudaFuncSetAttribute(bf_gemm<OUT_F32,   false, false>, cudaFuncAttributeMaxDynamicSharedMemorySize, SMEM_DYN);
    cudaFuncSetAttribute(bf_gemm<OUT_F32,   false, true >, cudaFuncAttributeMaxDynamicSharedMemorySize, SMEM_DYN);
    cudaFuncSetAttribute(bf_gemm<OUT_SPLIT, true,  false>, cudaFuncAttributeMaxDynamicSharedMemorySize, SMEM_DYN);

    // weight splits
    cvt_split<<<(En * En / 4 + 255) / 256, 256>>>((const float4*)wq, (__nv_bfloat162*)wqh, (__nv_bfloat162*)wql, En * En / 4);
    cvt_split<<<(En * En / 4 + 255) / 256, 256>>>((const float4*)wk, (__nv_bfloat162*)wkh, (__nv_bfloat162*)wkl, En * En / 4);
    cvt_split<<<(En * En / 4 + 255) / 256, 256>>>((const float4*)wv, (__nv_bfloat162*)wvh, (__nv_bfloat162*)wvl, En * En / 4);
    cvt_split<<<(En * En / 4 + 255) / 256, 256>>>((const float4*)wo, (__nv_bfloat162*)woh, (__nv_bfloat162*)wol, En * En / 4);
    cvt_split<<<(FFdim * En / 4 + 255) / 256, 256>>>((const float4*)w1, (__nv_bfloat162*)w1h, (__nv_bfloat162*)w1l, FFdim * En / 4);
    cvt_split<<<(FFdim * En / 4 + 255) / 256, 256>>>((const float4*)w2, (__nv_bfloat162*)w2h, (__nv_bfloat162*)w2l, FFdim * En / 4);

    // 1) LN1 -> split
    ln_split<<<Mtot, 256>>>(x, ln1w, ln1b, nxh, nxl);

    // 2-4) QKV projections (tensor cores via mma.sync)
    dim3 gProj(En / 128, Mtot / 128);
    bf_gemm<OUT_F32, false, false><<<gProj, 256, SMEM_DYN>>>(nxh, nxl, wqh, wql, bq, nullptr, q, nullptr, nullptr, Mtot, En, En);
    bf_gemm<OUT_F32, false, false><<<gProj, 256, SMEM_DYN>>>(nxh, nxl, wkh, wkl, bk, nullptr, k, nullptr, nullptr, Mtot, En, En);
    bf_gemm<OUT_F32, false, false><<<gProj, 256, SMEM_DYN>>>(nxh, nxl, wvh, wvl, bv, nullptr, v, nullptr, nullptr, Mtot, En, En);

    // 5) attention -> split bf16
    dim3 gAttn(Sn / 64, Hn, Bn);
    attn_kernel<<<gAttn, 64>>>(q, k, v, mask, aoh, aol);

    // 6) O projection + residual(x) -> x2 (fp32)
    bf_gemm<OUT_F32, false, true><<<gProj, 256, SMEM_DYN>>>(aoh, aol, woh, wol, bo, x, x2, nullptr, nullptr, Mtot, En, En);

    // 7) LN2 -> split
    ln_split<<<Mtot, 256>>>(x2, ln2w, ln2b, nx2h, nx2l);

    // 8) FFN1 + ReLU -> split bf16
    dim3 gF1(FFdim / 128, Mtot / 128);
    bf_gemm<OUT_SPLIT, true, false><<<gF1, 256, SMEM_DYN>>>(nx2h, nx2l, w1h, w1l, b1, nullptr, nullptr, hbh, hbl, Mtot, FFdim, En);

    // 9) FFN2 + residual(x2) -> out (fp32)
    dim3 gF2(En / 128, Mtot / 128);
    bf_gemm<OUT_F32, false, true><<<gF2, 256, SMEM_DYN>>>(hbh, hbl, w2h, w2l, b2, x2, out, nullptr, nullptr, Mtot, En, FFdim);
}